// round 1
// baseline (speedup 1.0000x reference)
#include <cuda_runtime.h>
#include <math.h>

#define Bn 8192
#define Dn 64
#define Cn 2048
static __device__ __constant__ float kEps = 1e-6f;
#define INV_SQRT_D 0.125f

// ---------------- scratch (no dynamic allocation allowed) ----------------
__device__ float g_xcan[Bn * Dn];   // canonicalized x
__device__ float g_c2[Cn];          // code squared norms
__device__ int   g_best[Bn];        // argmin indices
__device__ float g_loss;            // loss accumulator

// ---------------- helpers ----------------
__device__ __forceinline__ void fma2(unsigned long long& acc,
                                     unsigned long long a,
                                     unsigned long long b) {
    asm("fma.rn.f32x2 %0, %1, %2, %0;" : "+l"(acc) : "l"(a), "l"(b));
}
__device__ __forceinline__ float2 unpack2(unsigned long long v) {
    float2 r;
    asm("mov.b64 {%0, %1}, %2;" : "=f"(r.x), "=f"(r.y) : "l"(v));
    return r;
}

// ---------------- kernel 1: code norms + zero loss ----------------
__global__ void prep_kernel(const float* __restrict__ codes) {
    int c = blockIdx.x * blockDim.x + threadIdx.x;
    if (c == 0 && blockIdx.x == 0) g_loss = 0.0f;
    if (c < Cn) {
        const float4* p = reinterpret_cast<const float4*>(codes + c * Dn);
        float s = 0.0f;
#pragma unroll
        for (int i = 0; i < Dn / 4; i++) {
            float4 v = p[i];
            s += v.x * v.x + v.y * v.y + v.z * v.z + v.w * v.w;
        }
        g_c2[c] = s;
    }
}

// ---------------- kernel 2: canonicalize (one warp per row) ----------------
__global__ void canon_kernel(const float* __restrict__ x,
                             const float* __restrict__ pq) {
    int warp = (blockIdx.x * blockDim.x + threadIdx.x) >> 5;
    int lane = threadIdx.x & 31;
    if (warp >= Bn) return;
    const float* xr = x + warp * Dn;
    const float* pr = pq + warp * Dn;
    float x0 = xr[lane], x1 = xr[lane + 32];
    float p0 = pr[lane], p1 = pr[lane + 32];

    float n2 = p0 * p0 + p1 * p1;
#pragma unroll
    for (int o = 16; o; o >>= 1) n2 += __shfl_xor_sync(0xffffffffu, n2, o);
    float inv = 1.0f / fmaxf(sqrtf(n2), kEps);
    float u0 = p0 * inv, u1 = p1 * inv;

    float su = u0 + u1, sx = x0 + x1, ux = u0 * x0 + u1 * x1;
#pragma unroll
    for (int o = 16; o; o >>= 1) {
        su += __shfl_xor_sync(0xffffffffu, su, o);
        sx += __shfl_xor_sync(0xffffffffu, sx, o);
        ux += __shfl_xor_sync(0xffffffffu, ux, o);
    }
    float s = INV_SQRT_D * su;   // u.v
    float p = INV_SQRT_D * sx;   // v.x
    float q = ux;                // u.x
    float dd = 1.0f + s + kEps;
    float alpha = -p + (s * p - q) / dd;
    float beta  =  q - (p - s * q) / dd;

    g_xcan[warp * Dn + lane]      = x0 + alpha * u0 + beta * INV_SQRT_D;
    g_xcan[warp * Dn + lane + 32] = x1 + alpha * u1 + beta * INV_SQRT_D;
}

// ---------------- kernel 3: fused distance GEMM + argmin ----------------
// 256 blocks x 256 threads. Block = 32 rows x all 2048 codes (16 tiles of 128).
// Thread tile: 4 rows x 4 codes, packed f32x2 over the D dimension.
#define RPB 32
#define CT 128
#define PAD 129
__global__ __launch_bounds__(256, 2) void argmin_kernel(
    const float* __restrict__ codes) {
    __shared__ unsigned long long xs[RPB * 32];   // [r][d2], packed pair
    __shared__ unsigned long long cs[32 * PAD];   // [d2][c], pad 129
    __shared__ float c2s[CT];

    int tid = threadIdx.x;
    int lane = tid & 31;
    int w = tid >> 5;                 // warp 0..7 -> rows w*4..w*4+3
    int rowBase = blockIdx.x * RPB;

    // load x tile (packed pairs), coalesced global reads
    for (int k = tid; k < RPB * 32; k += 256) {
        int d2 = k & 31, r = k >> 5;
        xs[r * 32 + d2] = *reinterpret_cast<const unsigned long long*>(
            &g_xcan[(rowBase + r) * Dn + 2 * d2]);
    }

    float bestD[4];
    int bestI[4];
#pragma unroll
    for (int i = 0; i < 4; i++) { bestD[i] = INFINITY; bestI[i] = 0; }

    const int xbase = w * 4 * 32;

    for (int t = 0; t < Cn / CT; ++t) {
        __syncthreads();
        // stage code tile transposed [d2][c] as packed pairs
        for (int k = tid; k < CT * 32; k += 256) {
            int d2 = k & 31, c = k >> 5;
            cs[d2 * PAD + c] = *reinterpret_cast<const unsigned long long*>(
                &codes[(t * CT + c) * Dn + 2 * d2]);
        }
        if (tid < CT) c2s[tid] = g_c2[t * CT + tid];
        __syncthreads();

        unsigned long long acc[16];
#pragma unroll
        for (int i = 0; i < 16; i++) acc[i] = 0ull;

#pragma unroll 4
        for (int d2 = 0; d2 < 32; ++d2) {
            unsigned long long xv0 = xs[xbase + d2];
            unsigned long long xv1 = xs[xbase + 32 + d2];
            unsigned long long xv2 = xs[xbase + 64 + d2];
            unsigned long long xv3 = xs[xbase + 96 + d2];
            const unsigned long long* crow = cs + d2 * PAD + lane;
            unsigned long long cv0 = crow[0];
            unsigned long long cv1 = crow[32];
            unsigned long long cv2 = crow[64];
            unsigned long long cv3 = crow[96];
            fma2(acc[0],  xv0, cv0); fma2(acc[1],  xv0, cv1);
            fma2(acc[2],  xv0, cv2); fma2(acc[3],  xv0, cv3);
            fma2(acc[4],  xv1, cv0); fma2(acc[5],  xv1, cv1);
            fma2(acc[6],  xv1, cv2); fma2(acc[7],  xv1, cv3);
            fma2(acc[8],  xv2, cv0); fma2(acc[9],  xv2, cv1);
            fma2(acc[10], xv2, cv2); fma2(acc[11], xv2, cv3);
            fma2(acc[12], xv3, cv0); fma2(acc[13], xv3, cv1);
            fma2(acc[14], xv3, cv2); fma2(acc[15], xv3, cv3);
        }

#pragma unroll
        for (int i = 0; i < 4; i++) {
#pragma unroll
            for (int j = 0; j < 4; j++) {
                float2 f = unpack2(acc[i * 4 + j]);
                float dot = f.x + f.y;
                float dist = c2s[lane + 32 * j] - 2.0f * dot;
                int idx = t * CT + lane + 32 * j;
                if (dist < bestD[i]) { bestD[i] = dist; bestI[i] = idx; }
            }
        }
    }

    // cross-lane argmin (ties -> smaller index, matching argmin semantics)
#pragma unroll
    for (int i = 0; i < 4; i++) {
        float d = bestD[i];
        int ix = bestI[i];
#pragma unroll
        for (int off = 16; off; off >>= 1) {
            float od = __shfl_xor_sync(0xffffffffu, d, off);
            int oi = __shfl_xor_sync(0xffffffffu, ix, off);
            if (od < d || (od == d && oi < ix)) { d = od; ix = oi; }
        }
        if (lane == 0) g_best[rowBase + w * 4 + i] = ix;
    }
}

// ---------------- kernel 4: rotate back, write outputs, loss partials ----
__global__ void final_kernel(const float* __restrict__ x,
                             const float* __restrict__ pq,
                             const float* __restrict__ codes,
                             float* __restrict__ out,
                             int has_idx) {
    __shared__ float bl;
    int tid = threadIdx.x;
    if (tid == 0) bl = 0.0f;
    __syncthreads();

    int warp = (blockIdx.x * blockDim.x + tid) >> 5;
    int lane = tid & 31;
    if (warp < Bn) {
        int row = warp;
        int idx = g_best[row];
        const float* qcr = codes + idx * Dn;
        float qc0 = qcr[lane], qc1 = qcr[lane + 32];
        const float* pr = pq + row * Dn;
        float p0 = pr[lane], p1 = pr[lane + 32];

        float n2 = p0 * p0 + p1 * p1;
#pragma unroll
        for (int o = 16; o; o >>= 1) n2 += __shfl_xor_sync(0xffffffffu, n2, o);
        float inv = 1.0f / fmaxf(sqrtf(n2), kEps);
        float u0 = p0 * inv, u1 = p1 * inv;

        float su = u0 + u1, sq = qc0 + qc1, uq = u0 * qc0 + u1 * qc1;
#pragma unroll
        for (int o = 16; o; o >>= 1) {
            su += __shfl_xor_sync(0xffffffffu, su, o);
            sq += __shfl_xor_sync(0xffffffffu, sq, o);
            uq += __shfl_xor_sync(0xffffffffu, uq, o);
        }
        float s = INV_SQRT_D * su;
        float pp = INV_SQRT_D * sq;   // v . qc
        float qq = uq;                // u . qc
        float dd = 1.0f + s + kEps;
        float a = pp + (s * pp - qq) / dd;
        float b = -qq - (pp - s * qq) / dd;

        out[row * Dn + lane]      = qc0 + a * u0 + b * INV_SQRT_D;
        out[row * Dn + lane + 32] = qc1 + a * u1 + b * INV_SQRT_D;

        const float* xr = x + row * Dn;
        float x0 = xr[lane], x1 = xr[lane + 32];
        float l = (x0 - qc0) * (x0 - qc0) + (x1 - qc1) * (x1 - qc1);
#pragma unroll
        for (int o = 16; o; o >>= 1) l += __shfl_xor_sync(0xffffffffu, l, o);

        if (lane == 0) {
            if (has_idx) out[Bn * Dn + row] = (float)idx;
            atomicAdd(&bl, l);
        }
    }
    __syncthreads();
    if (tid == 0) atomicAdd(&g_loss, bl);
}

__global__ void loss_kernel(float* __restrict__ out) {
    out[Bn * Dn + Bn] = g_loss * (1.25f / (float)Bn);
}

// ---------------- launcher ----------------
extern "C" void kernel_launch(void* const* d_in, const int* in_sizes, int n_in,
                              void* d_out, int out_size) {
    const float* x     = (const float*)d_in[0];
    const float* pq    = (const float*)d_in[1];
    const float* codes = (const float*)d_in[2];
    float* out = (float*)d_out;

    int has_idx  = out_size >= Bn * Dn + Bn;
    int has_loss = out_size >= Bn * Dn + Bn + 1;

    prep_kernel<<<(Cn + 127) / 128, 128>>>(codes);
    canon_kernel<<<Bn / 8, 256>>>(x, pq);
    argmin_kernel<<<Bn / RPB, 256>>>(codes);
    final_kernel<<<Bn / 8, 256>>>(x, pq, codes, out, has_idx);
    if (has_loss) loss_kernel<<<1, 1>>>(out);
}

// round 2
// speedup vs baseline: 1.2918x; 1.2918x over previous
#include <cuda_runtime.h>
#include <math.h>

#define Bn 8192
#define Dn 64
#define Cn 2048
#define EPSf 1e-6f
#define INV_SQRT_D 0.125f

typedef unsigned long long u64;

// ---------------- scratch (no dynamic allocation allowed) ----------------
__device__ float g_xcan[Bn * Dn];   // canonicalized x
__device__ float g_c2[Cn];          // code squared norms
__device__ int   g_best[Bn];        // argmin indices
__device__ float g_loss;            // loss accumulator
__device__ unsigned int g_done;     // block arrival counter for loss finalize

// ---------------- helpers ----------------
__device__ __forceinline__ void fma2(u64& acc, u64 a, u64 b) {
    asm("fma.rn.f32x2 %0, %1, %2, %0;" : "+l"(acc) : "l"(a), "l"(b));
}
__device__ __forceinline__ float2 unpack2(u64 v) {
    float2 r;
    asm("mov.b64 {%0, %1}, %2;" : "=f"(r.x), "=f"(r.y) : "l"(v));
    return r;
}

// ---------------- kernel 1: canonicalize rows + (fused) code norms ----------
// blocks [0, Bn/8): one warp per row, canonicalize.
// blocks [Bn/8, Bn/8 + Cn/256): code squared norms + zero accumulators.
__global__ void canon_kernel(const float* __restrict__ x,
                             const float* __restrict__ pq,
                             const float* __restrict__ codes) {
    if (blockIdx.x >= Bn / 8) {
        int c = (blockIdx.x - Bn / 8) * 256 + threadIdx.x;
        if (blockIdx.x == Bn / 8 && threadIdx.x == 0) { g_loss = 0.0f; g_done = 0u; }
        if (c < Cn) {
            const float4* p = reinterpret_cast<const float4*>(codes + c * Dn);
            float s = 0.0f;
#pragma unroll
            for (int i = 0; i < Dn / 4; i++) {
                float4 v = p[i];
                s += v.x * v.x + v.y * v.y + v.z * v.z + v.w * v.w;
            }
            g_c2[c] = s;
        }
        return;
    }

    int warp = blockIdx.x * 8 + (threadIdx.x >> 5);
    int lane = threadIdx.x & 31;
    const float* xr = x + warp * Dn;
    const float* pr = pq + warp * Dn;
    float x0 = xr[lane], x1 = xr[lane + 32];
    float p0 = pr[lane], p1 = pr[lane + 32];

    // one-pass 4-value warp reduction
    float n2 = p0 * p0 + p1 * p1;
    float sp = p0 + p1;
    float sx = x0 + x1;
    float px = p0 * x0 + p1 * x1;
#pragma unroll
    for (int o = 16; o; o >>= 1) {
        n2 += __shfl_xor_sync(0xffffffffu, n2, o);
        sp += __shfl_xor_sync(0xffffffffu, sp, o);
        sx += __shfl_xor_sync(0xffffffffu, sx, o);
        px += __shfl_xor_sync(0xffffffffu, px, o);
    }
    float inv = 1.0f / fmaxf(sqrtf(n2), EPSf);
    float u0 = p0 * inv, u1 = p1 * inv;
    float s = INV_SQRT_D * sp * inv;    // u.v
    float p = INV_SQRT_D * sx;          // v.x
    float q = px * inv;                 // u.x
    float dd = 1.0f + s + EPSf;
    float alpha = -p + (s * p - q) / dd;
    float beta  =  q - (p - s * q) / dd;

    g_xcan[warp * Dn + lane]      = x0 + alpha * u0 + beta * INV_SQRT_D;
    g_xcan[warp * Dn + lane + 32] = x1 + alpha * u1 + beta * INV_SQRT_D;
}

// ---------------- kernel 2: fused distance GEMM + argmin ----------------
// 147 blocks x 256 threads, 1 block/SM. Block = 56 rows x all 2048 codes.
// Thread tile: 7 rows x 4 codes, packed f32x2, all smem traffic via LDS.128.
#define RPB 56
#define RPT 7
#define CT 128
#define NT (Cn / CT)
#define CS_STRIDE 258                 // u64 per p-row (128 codes * 2 + pad 2)
#define CS_BUF (16 * CS_STRIDE)       // 4128 u64 per buffer
#define XS_SIZE (RPB * 32)            // 1792 u64
#define SMEM_BYTES ((2 * CS_BUF + XS_SIZE) * 8 + 2 * CT * 4)

__global__ __launch_bounds__(256, 1) void argmin_kernel(
    const float* __restrict__ codes) {
    extern __shared__ u64 sm[];
    u64* cs = sm;                           // [2][16][CS_STRIDE]
    u64* xs = sm + 2 * CS_BUF;              // [RPB][32]
    float* c2s = (float*)(sm + 2 * CS_BUF + XS_SIZE);  // [2][CT]

    int tid = threadIdx.x;
    int lane = tid & 31;
    int w = tid >> 5;
    int rowBase = blockIdx.x * RPB;

    // stage x tile: [row][d2] packed pairs
    for (int idx = tid; idx < RPB * 16; idx += 256) {
        int r = idx >> 4, f4 = idx & 15;
        int grow = rowBase + r;
        if (grow > Bn - 1) grow = Bn - 1;
        float4 v = *reinterpret_cast<const float4*>(&g_xcan[grow * Dn + f4 * 4]);
        *reinterpret_cast<ulonglong2*>(&xs[r * 32 + f4 * 2]) =
            *reinterpret_cast<ulonglong2*>(&v);
    }
    // stage code tile 0: layout [p][code] of d2-pairs
    for (int idx = tid; idx < CT * 16; idx += 256) {
        int c = idx >> 4, f4 = idx & 15;
        float4 v = *reinterpret_cast<const float4*>(&codes[c * Dn + f4 * 4]);
        *reinterpret_cast<ulonglong2*>(&cs[f4 * CS_STRIDE + c * 2]) =
            *reinterpret_cast<ulonglong2*>(&v);
    }
    if (tid < CT) c2s[tid] = g_c2[tid];
    __syncthreads();

    float bestD[RPT];
    int bestI[RPT];
#pragma unroll
    for (int i = 0; i < RPT; i++) { bestD[i] = INFINITY; bestI[i] = 0; }

    int buf = 0;
    for (int t = 0; t < NT; ++t) {
        // register-prefetch next code tile
        float4 pf[8];
        float pc2 = 0.0f;
        if (t + 1 < NT) {
#pragma unroll
            for (int i = 0; i < 8; ++i) {
                int idx = tid + 256 * i;
                int c = idx >> 4, f4 = idx & 15;
                pf[i] = __ldg(reinterpret_cast<const float4*>(
                    &codes[((t + 1) * CT + c) * Dn + f4 * 4]));
            }
            if (tid < CT) pc2 = __ldg(&g_c2[(t + 1) * CT + tid]);
        }

        u64 acc[RPT][4];
#pragma unroll
        for (int i = 0; i < RPT; i++)
#pragma unroll
            for (int j = 0; j < 4; j++) acc[i][j] = 0ull;

        const u64* csb = cs + buf * CS_BUF;
#pragma unroll 4
        for (int p = 0; p < 16; ++p) {
            ulonglong2 cv[4];
#pragma unroll
            for (int j = 0; j < 4; ++j)
                cv[j] = *reinterpret_cast<const ulonglong2*>(
                    &csb[p * CS_STRIDE + (lane + 32 * j) * 2]);
#pragma unroll
            for (int i = 0; i < RPT; ++i) {
                ulonglong2 xv = *reinterpret_cast<const ulonglong2*>(
                    &xs[(w * RPT + i) * 32 + p * 2]);
#pragma unroll
                for (int j = 0; j < 4; ++j) {
                    fma2(acc[i][j], xv.x, cv[j].x);
                    fma2(acc[i][j], xv.y, cv[j].y);
                }
            }
        }

        // epilogue: dist = |c|^2 - 2 x.c   (x^2 constant per row, dropped)
        const float* c2b = c2s + buf * CT;
#pragma unroll
        for (int i = 0; i < RPT; ++i) {
#pragma unroll
            for (int j = 0; j < 4; ++j) {
                float2 f = unpack2(acc[i][j]);
                float dist = c2b[lane + 32 * j] - 2.0f * (f.x + f.y);
                int idx = t * CT + lane + 32 * j;
                if (dist < bestD[i]) { bestD[i] = dist; bestI[i] = idx; }
            }
        }

        // commit prefetched tile to the other buffer
        if (t + 1 < NT) {
            u64* csn = cs + (buf ^ 1) * CS_BUF;
#pragma unroll
            for (int i = 0; i < 8; ++i) {
                int idx = tid + 256 * i;
                int c = idx >> 4, f4 = idx & 15;
                *reinterpret_cast<ulonglong2*>(&csn[f4 * CS_STRIDE + c * 2]) =
                    *reinterpret_cast<ulonglong2*>(&pf[i]);
            }
            if (tid < CT) c2s[(buf ^ 1) * CT + tid] = pc2;
            buf ^= 1;
            __syncthreads();
        }
    }

    // cross-lane argmin (ties -> smaller index)
#pragma unroll
    for (int i = 0; i < RPT; ++i) {
        float d = bestD[i];
        int ix = bestI[i];
#pragma unroll
        for (int off = 16; off; off >>= 1) {
            float od = __shfl_xor_sync(0xffffffffu, d, off);
            int oi = __shfl_xor_sync(0xffffffffu, ix, off);
            if (od < d || (od == d && oi < ix)) { d = od; ix = oi; }
        }
        int grow = rowBase + w * RPT + i;
        if (lane == 0 && grow < Bn) g_best[grow] = ix;
    }
}

// ---------------- kernel 3: rotate back, outputs, loss (fused finalize) ----
__global__ void final_kernel(const float* __restrict__ x,
                             const float* __restrict__ pq,
                             const float* __restrict__ codes,
                             float* __restrict__ out,
                             int has_idx, int has_loss) {
    __shared__ float bl;
    int tid = threadIdx.x;
    if (tid == 0) bl = 0.0f;
    __syncthreads();

    int row = blockIdx.x * 8 + (tid >> 5);
    int lane = tid & 31;

    int idx = g_best[row];
    const float* qcr = codes + idx * Dn;
    float qc0 = qcr[lane], qc1 = qcr[lane + 32];
    const float* pr = pq + row * Dn;
    float p0 = pr[lane], p1 = pr[lane + 32];
    const float* xr = x + row * Dn;
    float x0 = xr[lane], x1 = xr[lane + 32];

    // one-pass 5-value warp reduction
    float n2 = p0 * p0 + p1 * p1;
    float sp = p0 + p1;
    float sq = qc0 + qc1;
    float pqv = p0 * qc0 + p1 * qc1;
    float l = (x0 - qc0) * (x0 - qc0) + (x1 - qc1) * (x1 - qc1);
#pragma unroll
    for (int o = 16; o; o >>= 1) {
        n2  += __shfl_xor_sync(0xffffffffu, n2, o);
        sp  += __shfl_xor_sync(0xffffffffu, sp, o);
        sq  += __shfl_xor_sync(0xffffffffu, sq, o);
        pqv += __shfl_xor_sync(0xffffffffu, pqv, o);
        l   += __shfl_xor_sync(0xffffffffu, l, o);
    }
    float inv = 1.0f / fmaxf(sqrtf(n2), EPSf);
    float u0 = p0 * inv, u1 = p1 * inv;
    float s  = INV_SQRT_D * sp * inv;   // u.v
    float pp = INV_SQRT_D * sq;         // v.qc
    float qq = pqv * inv;               // u.qc
    float dd = 1.0f + s + EPSf;
    float a = pp + (s * pp - qq) / dd;
    float b = -qq + (s * qq - pp) / dd;

    out[row * Dn + lane]      = qc0 + a * u0 + b * INV_SQRT_D;
    out[row * Dn + lane + 32] = qc1 + a * u1 + b * INV_SQRT_D;

    if (lane == 0) {
        if (has_idx) out[Bn * Dn + row] = (float)idx;
        atomicAdd(&bl, l);
    }
    __syncthreads();
    if (tid == 0) {
        atomicAdd(&g_loss, bl);
        __threadfence();
        unsigned int n = atomicAdd(&g_done, 1u);
        if (n == gridDim.x - 1) {
            g_done = 0u;
            __threadfence();
            if (has_loss) out[Bn * Dn + Bn] = g_loss * (1.25f / (float)Bn);
        }
    }
}

// ---------------- launcher ----------------
extern "C" void kernel_launch(void* const* d_in, const int* in_sizes, int n_in,
                              void* d_out, int out_size) {
    const float* x     = (const float*)d_in[0];
    const float* pq    = (const float*)d_in[1];
    const float* codes = (const float*)d_in[2];
    float* out = (float*)d_out;

    int has_idx  = out_size >= Bn * Dn + Bn;
    int has_loss = out_size >= Bn * Dn + Bn + 1;

    cudaFuncSetAttribute(argmin_kernel,
                         cudaFuncAttributeMaxDynamicSharedMemorySize, SMEM_BYTES);

    canon_kernel<<<Bn / 8 + Cn / 256, 256>>>(x, pq, codes);
    argmin_kernel<<<(Bn + RPB - 1) / RPB, 256, SMEM_BYTES>>>(codes);
    final_kernel<<<Bn / 8, 256>>>(x, pq, codes, out, has_idx, has_loss);
}

// round 4
// speedup vs baseline: 1.4122x; 1.0932x over previous
#include <cuda_runtime.h>
#include <cuda_bf16.h>
#include <math.h>
#include <stdint.h>

#define Bn 8192
#define Dn 64
#define Cn 2048
#define EPSf 1e-6f
#define INV_SQRT_D 0.125f

// ---------------- global scratch ----------------
__device__ float g_xcan[Bn * Dn];     // canonicalized x
__device__ float g_c2[Cn];            // code squared norms
__device__ int   g_candI[Bn * 16];    // top-2 per (row, 256-code block)
__device__ float g_loss;
__device__ unsigned int g_done;

// ---------------- helpers ----------------
__device__ __forceinline__ uint32_t smem_u32(const void* p) {
    uint32_t a;
    asm("{ .reg .u64 t; cvta.to.shared.u64 t, %1; cvt.u32.u64 %0, t; }"
        : "=r"(a) : "l"(p));
    return a;
}
__device__ __forceinline__ void ldmx4(uint32_t& r0, uint32_t& r1,
                                      uint32_t& r2, uint32_t& r3, uint32_t a) {
    asm volatile("ldmatrix.sync.aligned.m8n8.x4.shared.b16 {%0,%1,%2,%3}, [%4];"
                 : "=r"(r0), "=r"(r1), "=r"(r2), "=r"(r3) : "r"(a));
}
__device__ __forceinline__ void mma16816(float* c, const uint32_t* a,
                                         const uint32_t* b) {
    asm volatile(
        "mma.sync.aligned.m16n8k16.row.col.f32.bf16.bf16.f32 "
        "{%0,%1,%2,%3}, {%4,%5,%6,%7}, {%8,%9}, {%0,%1,%2,%3};"
        : "+f"(c[0]), "+f"(c[1]), "+f"(c[2]), "+f"(c[3])
        : "r"(a[0]), "r"(a[1]), "r"(a[2]), "r"(a[3]), "r"(b[0]), "r"(b[1]));
}
__device__ __forceinline__ uint32_t pack_bf2(__nv_bfloat16 a, __nv_bfloat16 b) {
    __nv_bfloat162 t(a, b);
    return *reinterpret_cast<uint32_t*>(&t);
}

// ---------------- kernel 1: canonicalize rows + code norms ----------------
__global__ void canon_kernel(const float* __restrict__ x,
                             const float* __restrict__ pq,
                             const float* __restrict__ codes) {
    if (blockIdx.x >= Bn / 8) {
        int c = (blockIdx.x - Bn / 8) * 256 + threadIdx.x;
        if (blockIdx.x == Bn / 8 && threadIdx.x == 0) { g_loss = 0.0f; g_done = 0u; }
        if (c < Cn) {
            const float4* p = reinterpret_cast<const float4*>(codes + c * Dn);
            float s = 0.0f;
#pragma unroll
            for (int i = 0; i < Dn / 4; i++) {
                float4 v = p[i];
                s += v.x * v.x + v.y * v.y + v.z * v.z + v.w * v.w;
            }
            g_c2[c] = s;
        }
        return;
    }

    int warp = blockIdx.x * 8 + (threadIdx.x >> 5);
    int lane = threadIdx.x & 31;
    const float* xr = x + warp * Dn;
    const float* pr = pq + warp * Dn;
    float x0 = xr[lane], x1 = xr[lane + 32];
    float p0 = pr[lane], p1 = pr[lane + 32];

    float n2 = p0 * p0 + p1 * p1;
    float sp = p0 + p1;
    float sx = x0 + x1;
    float px = p0 * x0 + p1 * x1;
#pragma unroll
    for (int o = 16; o; o >>= 1) {
        n2 += __shfl_xor_sync(0xffffffffu, n2, o);
        sp += __shfl_xor_sync(0xffffffffu, sp, o);
        sx += __shfl_xor_sync(0xffffffffu, sx, o);
        px += __shfl_xor_sync(0xffffffffu, px, o);
    }
    float inv = 1.0f / fmaxf(sqrtf(n2), EPSf);
    float u0 = p0 * inv, u1 = p1 * inv;
    float s = INV_SQRT_D * sp * inv;
    float p = INV_SQRT_D * sx;
    float q = px * inv;
    float dd = 1.0f + s + EPSf;
    float alpha = -p + (s * p - q) / dd;
    float beta  =  q - (p - s * q) / dd;

    g_xcan[warp * Dn + lane]      = x0 + alpha * u0 + beta * INV_SQRT_D;
    g_xcan[warp * Dn + lane + 32] = x1 + alpha * u1 + beta * INV_SQRT_D;
}

// ---------------- kernel 2: HMMA bf16x2-compensated distance + argmin -----
// grid 512 = 64 Mtiles(128 rows) x 8 Ntiles(256 codes); 256 threads (8 warps 2x4)
#define ROWB 272                       // padded row stride in bytes (136 bf16)
#define ASZ (128 * ROWB)               // 34816
#define BSZ (256 * ROWB)               // 69632
#define SMEMSZ (ASZ + BSZ + 256 * 4)

__global__ void __launch_bounds__(256, 1) argmin_kernel(
    const float* __restrict__ codes) {
    extern __shared__ char sm[];
    char* Asm = sm;
    char* Bsm = sm + ASZ;
    float* c2s = (float*)(sm + ASZ + BSZ);
    uint32_t* epi = (uint32_t*)sm;     // aliased onto A after compute

    const int tid = threadIdx.x;
    const int lane = tid & 31;
    const int wid = tid >> 5;
    const int wm = wid & 1;            // m-half (0/1) -> rows wm*64
    const int wn = wid >> 1;           // n-quarter   -> cols wn*64
    const int mb = blockIdx.x >> 3;
    const int nb = blockIdx.x & 7;

    const uint32_t smbA = smem_u32(Asm);
    const uint32_t smbB = smem_u32(Bsm);

    // stage A: 128 rows of x_can -> bf16 hi (cols 0..63) + mid (cols 64..127)
    for (int i = tid; i < 128 * 16; i += 256) {
        int r = i >> 4, f4 = i & 15;
        float4 v = *reinterpret_cast<const float4*>(
            &g_xcan[(mb * 128 + r) * Dn + f4 * 4]);
        __nv_bfloat16 h0 = __float2bfloat16(v.x), h1 = __float2bfloat16(v.y);
        __nv_bfloat16 h2 = __float2bfloat16(v.z), h3 = __float2bfloat16(v.w);
        __nv_bfloat16 m0 = __float2bfloat16(v.x - __bfloat162float(h0));
        __nv_bfloat16 m1 = __float2bfloat16(v.y - __bfloat162float(h1));
        __nv_bfloat16 m2 = __float2bfloat16(v.z - __bfloat162float(h2));
        __nv_bfloat16 m3 = __float2bfloat16(v.w - __bfloat162float(h3));
        uint2 hh = make_uint2(pack_bf2(h0, h1), pack_bf2(h2, h3));
        uint2 mm = make_uint2(pack_bf2(m0, m1), pack_bf2(m2, m3));
        *reinterpret_cast<uint2*>(Asm + r * ROWB + f4 * 8) = hh;
        *reinterpret_cast<uint2*>(Asm + r * ROWB + 128 + f4 * 8) = mm;
    }
    // stage B: 256 code rows -> hi | mid
    for (int i = tid; i < 256 * 16; i += 256) {
        int r = i >> 4, f4 = i & 15;
        float4 v = *reinterpret_cast<const float4*>(
            &codes[(nb * 256 + r) * Dn + f4 * 4]);
        __nv_bfloat16 h0 = __float2bfloat16(v.x), h1 = __float2bfloat16(v.y);
        __nv_bfloat16 h2 = __float2bfloat16(v.z), h3 = __float2bfloat16(v.w);
        __nv_bfloat16 m0 = __float2bfloat16(v.x - __bfloat162float(h0));
        __nv_bfloat16 m1 = __float2bfloat16(v.y - __bfloat162float(h1));
        __nv_bfloat16 m2 = __float2bfloat16(v.z - __bfloat162float(h2));
        __nv_bfloat16 m3 = __float2bfloat16(v.w - __bfloat162float(h3));
        uint2 hh = make_uint2(pack_bf2(h0, h1), pack_bf2(h2, h3));
        uint2 mm = make_uint2(pack_bf2(m0, m1), pack_bf2(m2, m3));
        *reinterpret_cast<uint2*>(Bsm + r * ROWB + f4 * 8) = hh;
        *reinterpret_cast<uint2*>(Bsm + r * ROWB + 128 + f4 * 8) = mm;
    }
    if (tid < 256) c2s[tid] = g_c2[nb * 256 + tid];
    __syncthreads();

    float acc[4][8][4];
#pragma unroll
    for (int i = 0; i < 4; i++)
#pragma unroll
        for (int j = 0; j < 8; j++)
#pragma unroll
            for (int k = 0; k < 4; k++) acc[i][j][k] = 0.0f;

    // 3 passes: xh.ch (A0,B0), xh.cm (A0,B64), xm.ch (A64,B0); 4 k16-steps each
#pragma unroll
    for (int pass = 0; pass < 3; ++pass) {
        const int aoff = (pass == 2) ? 128 : 0;       // byte offset (64 bf16)
        const int boff = (pass == 1) ? 128 : 0;
#pragma unroll
        for (int ks = 0; ks < 4; ++ks) {
            const int kb = ks * 32;                   // 16 bf16 = 32 bytes
            uint32_t a[4][4];
#pragma unroll
            for (int mi = 0; mi < 4; ++mi) {
                uint32_t addr = smbA + (wm * 64 + mi * 16 + (lane & 15)) * ROWB
                              + aoff + kb + ((lane >> 4) * 16);
                ldmx4(a[mi][0], a[mi][1], a[mi][2], a[mi][3], addr);
            }
            uint32_t b[8][2];
#pragma unroll
            for (int nj = 0; nj < 4; ++nj) {
                int nrow = wn * 64 + nj * 16 + (((lane >> 4) & 1) * 8) + (lane & 7);
                uint32_t addr = smbB + nrow * ROWB + boff + kb
                              + (((lane >> 3) & 1) * 16);
                ldmx4(b[nj * 2][0], b[nj * 2][1], b[nj * 2 + 1][0], b[nj * 2 + 1][1],
                      addr);
            }
#pragma unroll
            for (int mi = 0; mi < 4; ++mi)
#pragma unroll
                for (int nj = 0; nj < 8; ++nj)
                    mma16816(acc[mi][nj], a[mi], b[nj]);
        }
    }

    __syncthreads();   // done reading A/B; epi aliases A

    // epilogue: per (warp,row) top-2 over this warp's 64 cols
#pragma unroll
    for (int mi = 0; mi < 4; ++mi) {
#pragma unroll
        for (int h = 0; h < 2; ++h) {
            float d1 = INFINITY, d2 = INFINITY;
            int i1 = 0, i2 = 0;
#pragma unroll
            for (int nj = 0; nj < 8; ++nj) {
#pragma unroll
                for (int s = 0; s < 2; ++s) {
                    int cloc = wn * 64 + nj * 8 + 2 * (lane & 3) + s;
                    float d = fmaf(-2.0f, acc[mi][nj][h * 2 + s], c2s[cloc]);
                    int gi = nb * 256 + cloc;
                    if (d < d1) { d2 = d1; i2 = i1; d1 = d; i1 = gi; }
                    else if (d < d2) { d2 = d; i2 = gi; }
                }
            }
            // quad merge (lanes sharing a row)
#pragma unroll
            for (int off = 1; off <= 2; off <<= 1) {
                float od1 = __shfl_xor_sync(0xffffffffu, d1, off);
                int   oi1 = __shfl_xor_sync(0xffffffffu, i1, off);
                float od2 = __shfl_xor_sync(0xffffffffu, d2, off);
                int   oi2 = __shfl_xor_sync(0xffffffffu, i2, off);
                if (d1 <= od1) {
                    if (od1 < d2) { d2 = od1; i2 = oi1; }
                } else {
                    if (d1 <= od2) { d2 = d1; i2 = i1; }
                    else           { d2 = od2; i2 = oi2; }
                    d1 = od1; i1 = oi1;
                }
            }
            if ((lane & 3) == 0) {
                int rowL = wm * 64 + mi * 16 + (lane >> 2) + h * 8;
                uint32_t* e = epi + (rowL * 4 + wn) * 4;
                e[0] = __float_as_uint(d1); e[1] = (uint32_t)i1;
                e[2] = __float_as_uint(d2); e[3] = (uint32_t)i2;
            }
        }
    }
    __syncthreads();

    // merge 4 warps' top-2 -> block top-2 per row
    if (tid < 128) {
        float d1 = INFINITY, d2 = INFINITY;
        int i1 = 0, i2 = 0;
#pragma unroll
        for (int w = 0; w < 4; ++w) {
            const uint32_t* e = epi + (tid * 4 + w) * 4;
            float a1 = __uint_as_float(e[0]); int b1i = (int)e[1];
            float a2 = __uint_as_float(e[2]); int b2i = (int)e[3];
            if (a1 < d1) { d2 = d1; i2 = i1; d1 = a1; i1 = b1i; }
            else if (a1 < d2) { d2 = a1; i2 = b1i; }
            if (a2 < d1) { d2 = d1; i2 = i1; d1 = a2; i1 = b2i; }
            else if (a2 < d2) { d2 = a2; i2 = b2i; }
        }
        int rowG = mb * 128 + tid;
        g_candI[rowG * 16 + nb * 2 + 0] = i1;
        g_candI[rowG * 16 + nb * 2 + 1] = i2;
    }
}

// ---------------- kernel 3: exact rescore of 16 cands, rotate back, loss --
__global__ void final_kernel(const float* __restrict__ x,
                             const float* __restrict__ pq,
                             const float* __restrict__ codes,
                             float* __restrict__ out,
                             int has_idx, int has_loss) {
    __shared__ float bl;
    int tid = threadIdx.x;
    if (tid == 0) bl = 0.0f;
    __syncthreads();

    int row = blockIdx.x * 8 + (tid >> 5);
    int lane = tid & 31;

    int ci[16];
#pragma unroll
    for (int k = 0; k < 16; ++k) ci[k] = g_candI[row * 16 + k];
    float xc0 = g_xcan[row * Dn + lane], xc1 = g_xcan[row * Dn + lane + 32];
    float dk[16];
#pragma unroll
    for (int k = 0; k < 16; ++k) {
        const float* cr = codes + ci[k] * Dn;
        dk[k] = xc0 * cr[lane] + xc1 * cr[lane + 32];
    }
#pragma unroll
    for (int o = 16; o; o >>= 1) {
#pragma unroll
        for (int k = 0; k < 16; ++k)
            dk[k] += __shfl_xor_sync(0xffffffffu, dk[k], o);
    }
    int best = ci[0];
    float bd = g_c2[ci[0]] - 2.0f * dk[0];
#pragma unroll
    for (int k = 1; k < 16; ++k) {
        float d = g_c2[ci[k]] - 2.0f * dk[k];
        if (d < bd || (d == bd && ci[k] < best)) { bd = d; best = ci[k]; }
    }
    int idx = best;

    const float* qcr = codes + idx * Dn;
    float qc0 = qcr[lane], qc1 = qcr[lane + 32];
    const float* pr = pq + row * Dn;
    float p0 = pr[lane], p1 = pr[lane + 32];
    const float* xr = x + row * Dn;
    float x0 = xr[lane], x1 = xr[lane + 32];

    float n2 = p0 * p0 + p1 * p1;
    float sp = p0 + p1;
    float sq = qc0 + qc1;
    float pqv = p0 * qc0 + p1 * qc1;
    float l = (x0 - qc0) * (x0 - qc0) + (x1 - qc1) * (x1 - qc1);
#pragma unroll
    for (int o = 16; o; o >>= 1) {
        n2  += __shfl_xor_sync(0xffffffffu, n2, o);
        sp  += __shfl_xor_sync(0xffffffffu, sp, o);
        sq  += __shfl_xor_sync(0xffffffffu, sq, o);
        pqv += __shfl_xor_sync(0xffffffffu, pqv, o);
        l   += __shfl_xor_sync(0xffffffffu, l, o);
    }
    float inv = 1.0f / fmaxf(sqrtf(n2), EPSf);
    float u0 = p0 * inv, u1 = p1 * inv;
    float s  = INV_SQRT_D * sp * inv;
    float pp = INV_SQRT_D * sq;
    float qq = pqv * inv;
    float dd = 1.0f + s + EPSf;
    float a = pp + (s * pp - qq) / dd;
    float b = -qq + (s * qq - pp) / dd;

    out[row * Dn + lane]      = qc0 + a * u0 + b * INV_SQRT_D;
    out[row * Dn + lane + 32] = qc1 + a * u1 + b * INV_SQRT_D;

    if (lane == 0) {
        if (has_idx) out[Bn * Dn + row] = (float)idx;
        atomicAdd(&bl, l);
    }
    __syncthreads();
    if (tid == 0) {
        atomicAdd(&g_loss, bl);
        __threadfence();
        unsigned int n = atomicAdd(&g_done, 1u);
        if (n == gridDim.x - 1) {
            g_done = 0u;
            __threadfence();
            if (has_loss) out[Bn * Dn + Bn] = g_loss * (1.25f / (float)Bn);
        }
    }
}

// ---------------- launcher ----------------
extern "C" void kernel_launch(void* const* d_in, const int* in_sizes, int n_in,
                              void* d_out, int out_size) {
    const float* x     = (const float*)d_in[0];
    const float* pq    = (const float*)d_in[1];
    const float* codes = (const float*)d_in[2];
    float* out = (float*)d_out;

    int has_idx  = out_size >= Bn * Dn + Bn;
    int has_loss = out_size >= Bn * Dn + Bn + 1;

    cudaFuncSetAttribute(argmin_kernel,
                         cudaFuncAttributeMaxDynamicSharedMemorySize, SMEMSZ);

    canon_kernel<<<Bn / 8 + Cn / 256, 256>>>(x, pq, codes);
    argmin_kernel<<<(Bn / 128) * (Cn / 256), 256, SMEMSZ>>>(codes);
    final_kernel<<<Bn / 8, 256>>>(x, pq, codes, out, has_idx, has_loss);
}